// round 1
// baseline (speedup 1.0000x reference)
#include <cuda_runtime.h>

// Causal depthwise conv1d (K=4) + SiLU.
// x: (B, T, C) fp32, weight: (C, K) fp32, bias: (C,) fp32 -> y: (B, T, C) fp32
// y[b,t,c] = silu( bias[c] + sum_k w[c,k] * x[b, t-3+k, c] )
//
// Strategy: float4 over C (coalesced), register sliding window over TT time
// steps per thread -> read amplification (TT+3)/TT, write 1x. HBM-bound.

constexpr int KTAPS = 4;
constexpr int TT    = 16;   // time steps per thread
constexpr int TPB   = 128;  // threads per block (covers 128 float4 channel groups)

__device__ __forceinline__ float silu(float v) {
    return v / (1.0f + __expf(-v));
}

__global__ __launch_bounds__(TPB)
void shortconv1d_kernel(const float* __restrict__ x,
                        const float* __restrict__ w,
                        const float* __restrict__ bias,
                        float* __restrict__ y,
                        int T, int C) {
    const int Cd4 = C >> 2;
    const int c4  = blockIdx.x * TPB + threadIdx.x;  // float4 channel-group index
    if (c4 >= Cd4) return;
    const int c   = c4 << 2;                          // base channel
    const int b   = blockIdx.z;
    const int t0  = blockIdx.y * TT;

    const float4* __restrict__ x4 = reinterpret_cast<const float4*>(x);
    float4* __restrict__       y4 = reinterpret_cast<float4*>(y);

    // Weight row for channel (c+j) is 4 contiguous floats == one float4.
    const float4* __restrict__ w4 = reinterpret_cast<const float4*>(w);
    float4 wl0 = w4[c + 0];
    float4 wl1 = w4[c + 1];
    float4 wl2 = w4[c + 2];
    float4 wl3 = w4[c + 3];
    float4 bi  = reinterpret_cast<const float4*>(bias)[c4];

    const size_t rowStride = (size_t)Cd4;             // float4 elements per time step
    const size_t baseBT    = (size_t)b * T;

    // History window: x[t0-3], x[t0-2], x[t0-1] (zero outside tensor).
    float4 h0, h1, h2;
    {
        const float4 z = make_float4(0.f, 0.f, 0.f, 0.f);
        int tm;
        tm = t0 - 3; h0 = (tm >= 0) ? x4[(baseBT + tm) * rowStride + c4] : z;
        tm = t0 - 2; h1 = (tm >= 0) ? x4[(baseBT + tm) * rowStride + c4] : z;
        tm = t0 - 1; h2 = (tm >= 0) ? x4[(baseBT + tm) * rowStride + c4] : z;
    }

#pragma unroll
    for (int i = 0; i < TT; ++i) {
        const int t = t0 + i;
        const float4 cur = x4[(baseBT + t) * rowStride + c4];

        float4 acc;
        acc.x = fmaf(wl0.x, h0.x, fmaf(wl0.y, h1.x, fmaf(wl0.z, h2.x, fmaf(wl0.w, cur.x, bi.x))));
        acc.y = fmaf(wl1.x, h0.y, fmaf(wl1.y, h1.y, fmaf(wl1.z, h2.y, fmaf(wl1.w, cur.y, bi.y))));
        acc.z = fmaf(wl2.x, h0.z, fmaf(wl2.y, h1.z, fmaf(wl2.z, h2.z, fmaf(wl2.w, cur.z, bi.z))));
        acc.w = fmaf(wl3.x, h0.w, fmaf(wl3.y, h1.w, fmaf(wl3.z, h2.w, fmaf(wl3.w, cur.w, bi.w))));

        float4 out;
        out.x = silu(acc.x);
        out.y = silu(acc.y);
        out.z = silu(acc.z);
        out.w = silu(acc.w);

        y4[(baseBT + t) * rowStride + c4] = out;

        h0 = h1; h1 = h2; h2 = cur;
    }
}

extern "C" void kernel_launch(void* const* d_in, const int* in_sizes, int n_in,
                              void* d_out, int out_size) {
    const float* x    = (const float*)d_in[0];
    const float* w    = (const float*)d_in[1];
    const float* bias = (const float*)d_in[2];
    float* y          = (float*)d_out;

    // Shapes fixed by the problem: B=4, T=4096, C=2048. Recover defensively:
    const int C = in_sizes[2];               // bias has C elements
    const int K = in_sizes[1] / C;           // weight is (C, K)
    (void)K;
    const int BT = in_sizes[0] / C;          // B*T
    const int T  = 4096;
    const int B  = BT / T;

    dim3 block(TPB);
    dim3 grid((C / 4 + TPB - 1) / TPB, T / TT, B);
    shortconv1d_kernel<<<grid, block>>>(x, w, bias, y, T, C);
}

// round 3
// speedup vs baseline: 1.3198x; 1.3198x over previous
#include <cuda_runtime.h>

// Causal depthwise conv1d (K=4) + SiLU, fp32.
// y[b,t,c] = silu( bias[c] + sum_k w[c,k] * x[b, t-3+k, c] )
//
// R2 strategy: front-batched register window (TT+3 float4 loads issued as one
// LDG burst -> high MLP), TT=8 for 2x thread count vs R1, streaming stores.

constexpr int TT  = 8;    // time steps per thread
constexpr int NW  = TT + 3;  // window loads per thread
constexpr int TPB = 256;  // threads per block

__device__ __forceinline__ float silu(float v) {
    return v / (1.0f + __expf(-v));
}

__device__ __forceinline__ void store_cs(float4* p, float4 v) {
    asm volatile("st.global.cs.v4.f32 [%0], {%1,%2,%3,%4};"
                 :: "l"(p), "f"(v.x), "f"(v.y), "f"(v.z), "f"(v.w) : "memory");
}

__global__ __launch_bounds__(TPB)
void shortconv1d_kernel(const float* __restrict__ x,
                        const float* __restrict__ w,
                        const float* __restrict__ bias,
                        float* __restrict__ y,
                        int T, int C) {
    const int Cd4 = C >> 2;
    const int c4  = blockIdx.x * TPB + threadIdx.x;  // float4 channel-group index
    if (c4 >= Cd4) return;
    const int c   = c4 << 2;
    const int b   = blockIdx.z;
    const int t0  = blockIdx.y * TT;

    const float4* __restrict__ x4 = reinterpret_cast<const float4*>(x);
    float4* __restrict__       y4 = reinterpret_cast<float4*>(y);

    const size_t rowStride = (size_t)Cd4;
    const size_t base      = ((size_t)b * T) * rowStride + c4;

    // ---- Front-batched load burst: window x[t0-3 .. t0+TT-1] ----
    float4 v[NW];
    const float4 z = make_float4(0.f, 0.f, 0.f, 0.f);
    if (t0 >= 3) {
#pragma unroll
        for (int i = 0; i < NW; ++i)
            v[i] = x4[base + (size_t)(t0 - 3 + i) * rowStride];
    } else {
#pragma unroll
        for (int i = 0; i < NW; ++i) {
            const int t = t0 - 3 + i;
            v[i] = (t >= 0) ? x4[base + (size_t)t * rowStride] : z;
        }
    }

    // ---- Weights (per-channel rows are contiguous float4) + bias ----
    const float4* __restrict__ w4 = reinterpret_cast<const float4*>(w);
    const float4 wl0 = w4[c + 0];
    const float4 wl1 = w4[c + 1];
    const float4 wl2 = w4[c + 2];
    const float4 wl3 = w4[c + 3];
    const float4 bi  = reinterpret_cast<const float4*>(bias)[c4];

    // ---- Compute + streaming stores ----
#pragma unroll
    for (int i = 0; i < TT; ++i) {
        const float4 a0 = v[i], a1 = v[i + 1], a2 = v[i + 2], a3 = v[i + 3];
        float4 acc;
        acc.x = fmaf(wl0.x, a0.x, fmaf(wl0.y, a1.x, fmaf(wl0.z, a2.x, fmaf(wl0.w, a3.x, bi.x))));
        acc.y = fmaf(wl1.x, a0.y, fmaf(wl1.y, a1.y, fmaf(wl1.z, a2.y, fmaf(wl1.w, a3.y, bi.y))));
        acc.z = fmaf(wl2.x, a0.z, fmaf(wl2.y, a1.z, fmaf(wl2.z, a2.z, fmaf(wl2.w, a3.z, bi.z))));
        acc.w = fmaf(wl3.x, a0.w, fmaf(wl3.y, a1.w, fmaf(wl3.z, a2.w, fmaf(wl3.w, a3.w, bi.w))));

        float4 out;
        out.x = silu(acc.x);
        out.y = silu(acc.y);
        out.z = silu(acc.z);
        out.w = silu(acc.w);

        store_cs(&y4[base + (size_t)(t0 + i) * rowStride], out);
    }
}

extern "C" void kernel_launch(void* const* d_in, const int* in_sizes, int n_in,
                              void* d_out, int out_size) {
    const float* x    = (const float*)d_in[0];
    const float* w    = (const float*)d_in[1];
    const float* bias = (const float*)d_in[2];
    float* y          = (float*)d_out;

    const int C  = in_sizes[2];       // bias: (C,)
    const int BT = in_sizes[0] / C;   // B*T
    const int T  = 4096;
    const int B  = BT / T;

    dim3 block(TPB);
    dim3 grid((C / 4 + TPB - 1) / TPB, T / TT, B);
    shortconv1d_kernel<<<grid, block>>>(x, w, bias, y, T, C);
}